// round 17
// baseline (speedup 1.0000x reference)
#include <cuda_runtime.h>
#include <cuda_bf16.h>
#include <math.h>

// Problem constants (fixed-shape problem: N=2,000,000, P=64, C=100)
#define CLS 100
#define FEAT 64
#define HFEAT 32         // features per warp (half a row, 1 float per lane)
#define BLOCK 512
#define WARPS 16         // warps per block, each with a private smem s-buffer
#define UNROLL 32        // rows per warp-stream per iteration (MLP)
#define MAIN_GRID 152    // GB300 has 152 SMs; 1 block/SM (smem-limited)
#define HB 256           // histogram blocks (per-block partial counts)

// Global scratch (allocation-free rule: __device__ globals)
__device__ float g_s[CLS * FEAT];   // per-class per-feature sums
__device__ float g_A;               // sum of ||x_row||^2 / (n_c - 1)
__device__ int   g_part[HB * CLS];  // per-hist-block partial counts (overwritten)
__device__ int   g_done;            // completion counter for fused finalize

// ---------------------------------------------------------------------------
// Sniff helper: t values are in [0,100); if int64, every high 32-bit word is
// 0. 64 random int32 labels all being 0 has prob ~1e-128.
// ---------------------------------------------------------------------------
__device__ __forceinline__ int sniff_is64(const void* t_raw) {
    const int* w = (const int*)t_raw;
    int z = 1;
    #pragma unroll
    for (int k = 0; k < 64; k++) z &= (w[2 * k + 1] == 0);
    return z;
}

// ---------------------------------------------------------------------------
// Kernel 1: class histogram over t (8/16 MB read). Each block OVERWRITES its
// private partial histogram slot (no global atomics, no pre-zeroing needed).
// Block 0 additionally zeroes main-kernel scratch (g_s, g_A, g_done) — safe
// because only main_kernel touches those and kernel ordering serializes.
// ---------------------------------------------------------------------------
__global__ void hist_kernel(const void* __restrict__ t_raw, int n) {
    __shared__ int h[CLS];
    __shared__ int s_is64;
    for (int i = threadIdx.x; i < CLS; i += blockDim.x) h[i] = 0;
    if (threadIdx.x == 0) s_is64 = sniff_is64(t_raw);
    if (blockIdx.x == 0) {
        for (int i = threadIdx.x; i < CLS * FEAT; i += blockDim.x) g_s[i] = 0.0f;
        if (threadIdx.x == 0) { g_A = 0.0f; g_done = 0; }
    }
    __syncthreads();
    const int is64 = s_is64;
    int i0 = blockIdx.x * blockDim.x + threadIdx.x;
    int stride = gridDim.x * blockDim.x;
    if (is64) {
        const long long* t = (const long long*)t_raw;
        for (int i = i0; i < n; i += stride) atomicAdd(&h[(int)t[i]], 1);
    } else {
        const int* t = (const int*)t_raw;
        for (int i = i0; i < n; i += stride) atomicAdd(&h[t[i]], 1);
    }
    __syncthreads();
    for (int i = threadIdx.x; i < CLS; i += blockDim.x)
        g_part[blockIdx.x * CLS + i] = h[i];
}

// ---------------------------------------------------------------------------
// Kernel 2: main pass over x (512 MB) + fused finalize (last block).
// A PAIR of warps covers one row stream: warp with (warp&1)==h handles
// features [h*32, h*32+32). Each warp has a PRIVATE CLS x 32 float smem
// buffer -> lane-disjoint non-atomic RMW, no conflicts. UNROLL=32 with
// hoisted bounds check; t loads vectorized via int4 (4 classes/load int32,
// 2/load int64). Per-lane register accumulates ||x||^2 * 1/(n_c-1).
// ---------------------------------------------------------------------------
__global__ __launch_bounds__(BLOCK, 1)
void main_kernel(const float* __restrict__ x, const void* __restrict__ t_raw,
                 int nRows, float* __restrict__ out) {
    extern __shared__ float smem[];
    __shared__ int isLast;
    __shared__ int s_is64;
    // layout: [WARPS][CLS*HFEAT] warp-private sum buffers, wcls[CLS], wcnt[CLS]
    const int lane = threadIdx.x & 31;
    const int warp = threadIdx.x >> 5;
    const int half = warp & 1;
    float* wbuf = smem + warp * (CLS * HFEAT);
    float* wcls = smem + WARPS * (CLS * HFEAT);
    float* wcnt = wcls + CLS;

    for (int i = threadIdx.x; i < WARPS * CLS * HFEAT; i += BLOCK) smem[i] = 0.0f;
    if (threadIdx.x == 0) s_is64 = sniff_is64(t_raw);
    // sum the HB partial histograms -> counts; stash counts + 1/(n-1)
    for (int i = threadIdx.x; i < CLS; i += BLOCK) {
        int cnt = 0;
        #pragma unroll 8
        for (int b = 0; b < HB; b++) cnt += g_part[b * CLS + i];
        wcnt[i] = (float)cnt;
        wcls[i] = 1.0f / ((float)cnt - 1.0f);
    }
    __syncthreads();

    const int is64 = s_is64;
    const long long* t64 = (const long long*)t_raw;
    const int* t32 = (const int*)t_raw;

    // column this lane reads within each row
    const int col = half * HFEAT + lane;
    const int totalStreams = (gridDim.x * WARPS) >> 1;
    const int stream = (blockIdx.x * WARPS + warp) >> 1;
    float acc = 0.0f;

    for (int r0 = stream * UNROLL; r0 < nRows; r0 += totalStreams * UNROLL) {
        if (r0 + UNROLL <= nRows) {
            // Full batch: no per-row bounds checks; vectorized t; batched x.
            float v[UNROLL];
            int c[UNROLL];
            if (is64) {
                const int4* tp = (const int4*)(t64 + r0);  // 2 int64 per int4
                #pragma unroll
                for (int i = 0; i < UNROLL / 2; i++) {
                    int4 q = tp[i];
                    c[2 * i] = q.x;      // low word of t64[r0+2i]
                    c[2 * i + 1] = q.z;  // low word of t64[r0+2i+1]
                }
            } else {
                const int4* tp = (const int4*)(t32 + r0);  // 4 int32 per int4
                #pragma unroll
                for (int i = 0; i < UNROLL / 4; i++) {
                    int4 q = tp[i];
                    c[4 * i] = q.x; c[4 * i + 1] = q.y;
                    c[4 * i + 2] = q.z; c[4 * i + 3] = q.w;
                }
            }
            const float* xp = x + (size_t)r0 * FEAT + col;
            #pragma unroll
            for (int i = 0; i < UNROLL; i++) v[i] = xp[i * FEAT];
            #pragma unroll
            for (int i = 0; i < UNROLL; i++) {
                float w = wcls[c[i]];
                float* p = wbuf + c[i] * HFEAT + lane;
                *p += v[i];
                acc = fmaf(v[i] * v[i], w, acc);
            }
        } else {
            // Tail batch: scalar path with bounds checks.
            for (int i = 0; i < UNROLL; i++) {
                int r = r0 + i;
                if (r < nRows) {
                    int cc = is64 ? (int)t64[r] : t32[r];
                    float vv = x[(size_t)r * FEAT + col];
                    float w = wcls[cc];
                    float* p = wbuf + cc * HFEAT + lane;
                    *p += vv;
                    acc = fmaf(vv * vv, w, acc);
                }
            }
        }
    }

    // warp-reduce acc, one global atomic per warp
    #pragma unroll
    for (int o = 16; o; o >>= 1) acc += __shfl_xor_sync(0xffffffffu, acc, o);
    if (lane == 0) atomicAdd(&g_A, acc);
    __syncthreads();

    // reduce the WARPS private copies -> global s.
    // global slot i maps to (class, feat); warps with (warp&1)==feat/32 hold it.
    for (int i = threadIdx.x; i < CLS * FEAT; i += BLOCK) {
        int cls = i / FEAT;
        int f = i % FEAT;
        int h = f / HFEAT;
        int fi = f % HFEAT;
        float s = 0.0f;
        #pragma unroll
        for (int wp = 0; wp < WARPS / 2; wp++)
            s += smem[(2 * wp + h) * (CLS * HFEAT) + cls * HFEAT + fi];
        atomicAdd(&g_s[i], s);
    }

    // ---- fused finalize: last block computes the scalar output ----
    __threadfence();
    __syncthreads();
    if (threadIdx.x == 0)
        isLast = (atomicAdd(&g_done, 1) == (int)gridDim.x - 1);
    __syncthreads();
    if (isLast) {
        __threadfence();  // acquire: all other blocks' g_s/g_A adds visible
        float* red = smem;  // wbuf no longer needed (wcls/wcnt region untouched)
        float b = 0.0f;
        for (int i = threadIdx.x; i < CLS * FEAT; i += BLOCK) {
            float n = wcnt[i / FEAT];
            float s = g_s[i];
            b += s * s / (n * (n - 1.0f));
        }
        __syncthreads();
        red[threadIdx.x] = b;
        __syncthreads();
        for (int st = BLOCK / 2; st; st >>= 1) {
            if (threadIdx.x < st) red[threadIdx.x] += red[threadIdx.x + st];
            __syncthreads();
        }
        if (threadIdx.x == 0) out[0] = (g_A - red[0]) / (float)CLS;
    }
}

// ---------------------------------------------------------------------------
extern "C" void kernel_launch(void* const* d_in, const int* in_sizes, int n_in,
                              void* d_out, int out_size) {
    const float* x = (const float*)d_in[0];
    const void* t = d_in[1];
    int nRows = in_sizes[0] / FEAT;

    const int smem_bytes = (WARPS * CLS * HFEAT + 2 * CLS) * (int)sizeof(float);
    cudaFuncSetAttribute(main_kernel,
                         cudaFuncAttributeMaxDynamicSharedMemorySize,
                         smem_bytes);

    hist_kernel<<<HB, 256>>>(t, nRows);
    main_kernel<<<MAIN_GRID, BLOCK, smem_bytes>>>(x, t, nRows, (float*)d_out);
}